// round 7
// baseline (speedup 1.0000x reference)
#include <cuda_runtime.h>
#include <cuda_bf16.h>

// pred (16,54,192,192) f32, target (16,6,192,192) f32, loc unused.
// loss = [ bce_sum(pred[:,0:18:2], target[:,0:1]) +
//          bce_sum(pred[:,1:18:2], target[:,1:2]) ] / 9
// Pred channel ch (0..17) pairs with target channel (ch & 1).
// Per element: max(x,0) - x*t + log1p(exp(-|x|)).
// log trick: sum_i log1p(e_i) = ln( prod_i (1+e_i) ), e_i in (0,1] so a
// 4-element product is in (1,16] -> one LG2 per float4.

namespace {
constexpr int B        = 16;
constexpr int HW4      = 192 * 192 / 4;      // 9216 float4 per channel slice
constexpr int NCH      = 18;
constexpr int PRED_CH  = 54;
constexpr int TGT_CH   = 6;

constexpr int TPB      = 256;
constexpr int SPLIT    = 4;                  // hw chunks per slice
constexpr int CHUNK4   = HW4 / SPLIT;        // 2304 float4 per block
constexpr int ITERS    = CHUNK4 / TPB;       // 9 stages of work per thread
constexpr int NSLICES  = B * NCH;            // 288
constexpr int NBLOCKS  = NSLICES * SPLIT;    // 1152 (one wave @ 8 blk/SM)

constexpr int STAGES   = 3;                  // cp.async ring depth
}

__device__ float        g_partials[NBLOCKS];
__device__ unsigned int g_count = 0;

__device__ __forceinline__ void cp16(void* smem_dst, const void* gmem_src) {
    unsigned s = (unsigned)__cvta_generic_to_shared(smem_dst);
    asm volatile("cp.async.cg.shared.global [%0], [%1], 16;"
                 :: "r"(s), "l"(gmem_src) : "memory");
}
__device__ __forceinline__ void cp_commit() {
    asm volatile("cp.async.commit_group;" ::: "memory");
}

__device__ __forceinline__ float block_reduce(float acc) {
    #pragma unroll
    for (int o = 16; o > 0; o >>= 1)
        acc += __shfl_xor_sync(0xffffffffu, acc, o);
    __shared__ float s[TPB / 32];
    if ((threadIdx.x & 31) == 0) s[threadIdx.x >> 5] = acc;
    __syncthreads();
    float v = 0.0f;
    if (threadIdx.x < 32) {
        v = (threadIdx.x < TPB / 32) ? s[threadIdx.x] : 0.0f;
        #pragma unroll
        for (int o = 4; o > 0; o >>= 1)
            v += __shfl_xor_sync(0xffffffffu, v, o);
    }
    return v;  // valid in thread 0
}

__global__ __launch_bounds__(TPB, 8)
void rpn_bce_fused(const float4* __restrict__ pred,
                   const float4* __restrict__ target,
                   float* __restrict__ out) {
    __shared__ float4 s_p[STAGES][TPB];   // 12 KB
    __shared__ float4 s_t[STAGES][TPB];   // 12 KB  (24 KB/blk * 8 = 192 KB/SM)

    const int tid   = threadIdx.x;
    const int bid   = blockIdx.x;
    const int chunk = bid % SPLIT;
    const int slice = bid / SPLIT;           // 0..287
    const int ch    = slice % NCH;           // pred channel 0..17
    const int b     = slice / NCH;

    const float4* __restrict__ p =
        pred + ((size_t)b * PRED_CH + ch) * HW4 + (size_t)chunk * CHUNK4 + tid;
    const float4* __restrict__ t =
        target + ((size_t)b * TGT_CH + (ch & 1)) * HW4
               + (size_t)chunk * CHUNK4 + tid;

    // Prologue: launch STAGES-1 stages. Each thread owns exactly its own
    // 16B slot per array per stage -> no cross-thread smem sharing, so the
    // whole pipeline needs NO __syncthreads.
    #pragma unroll
    for (int s = 0; s < STAGES - 1; ++s) {
        cp16(&s_p[s][tid], p + s * TPB);
        cp16(&s_t[s][tid], t + s * TPB);
        cp_commit();
    }

    constexpr float NL2E = -1.44269504088896341f;  // -log2(e)
    float acc  = 0.0f;   // sum of max(x,0) - x*t
    float lacc = 0.0f;   // sum of log2( prod4 (1+e) )

    #pragma unroll
    for (int i = 0; i < ITERS; ++i) {
        if (i == ITERS - 1)
            asm volatile("cp.async.wait_group 0;" ::: "memory");
        else
            asm volatile("cp.async.wait_group 1;" ::: "memory");

        const int buf = i % STAGES;
        const float4 x = s_p[buf][tid];
        const float4 y = s_t[buf][tid];

        // Refill the buffer consumed in iteration i-1 ((i+2)%STAGES).
        if (i + STAGES - 1 < ITERS) {
            const int nbuf = (i + STAGES - 1) % STAGES;
            cp16(&s_p[nbuf][tid], p + (i + STAGES - 1) * TPB);
            cp16(&s_t[nbuf][tid], t + (i + STAGES - 1) * TPB);
            cp_commit();
        }

        const float e0 = exp2f(fabsf(x.x) * NL2E);
        const float e1 = exp2f(fabsf(x.y) * NL2E);
        const float e2 = exp2f(fabsf(x.z) * NL2E);
        const float e3 = exp2f(fabsf(x.w) * NL2E);

        float pr = 1.0f + e0;
        pr = fmaf(pr, e1, pr);
        pr = fmaf(pr, e2, pr);
        pr = fmaf(pr, e3, pr);
        lacc += __log2f(pr);                 // one LG2 per 4 elements

        acc += fmaxf(x.x, 0.0f); acc = fmaf(-x.x, y.x, acc);
        acc += fmaxf(x.y, 0.0f); acc = fmaf(-x.y, y.y, acc);
        acc += fmaxf(x.z, 0.0f); acc = fmaf(-x.z, y.z, acc);
        acc += fmaxf(x.w, 0.0f); acc = fmaf(-x.w, y.w, acc);
    }

    const float v = block_reduce(fmaf(0.693147180559945f, lacc, acc));

    // Last-block-done deterministic finalize.
    __shared__ bool s_last;
    if (tid == 0) {
        g_partials[bid] = v;
        __threadfence();
        unsigned int n = atomicAdd(&g_count, 1u);
        s_last = (n == (unsigned int)(NBLOCKS - 1));
    }
    __syncthreads();

    if (s_last) {
        __threadfence();
        float a = 0.0f;
        #pragma unroll
        for (int i = tid; i < NBLOCKS; i += TPB)
            a += g_partials[i];
        const float total = block_reduce(a);
        if (tid == 0) {
            out[0] = total * (1.0f / 9.0f);  // / NUM_OBJ_CLS
            g_count = 0;                     // reset for graph replays
        }
    }
}

extern "C" void kernel_launch(void* const* d_in, const int* in_sizes, int n_in,
                              void* d_out, int out_size) {
    (void)in_sizes; (void)n_in; (void)out_size;
    const float4* pred   = (const float4*)d_in[0];
    const float4* target = (const float4*)d_in[1];
    float* out = (float*)d_out;

    rpn_bce_fused<<<NBLOCKS, TPB>>>(pred, target, out);
}

// round 8
// speedup vs baseline: 1.0909x; 1.0909x over previous
#include <cuda_runtime.h>
#include <cuda_bf16.h>
#include <cstdint>

// pred (16,54,192,192) f32, target (16,6,192,192) f32, loc unused.
// loss = [ bce_sum(pred[:,0:18:2], target[:,0:1]) +
//          bce_sum(pred[:,1:18:2], target[:,1:2]) ] / 9
// Pred channel ch (0..17) pairs with target channel (ch & 1).
// Per element: max(x,0) - x*t + log1p(exp(-|x|)).
// log trick: sum_i log1p(e_i) = ln( prod4 (1+e_i) ) -> one LG2 per float4.

namespace {
constexpr int B        = 16;
constexpr int HW4      = 192 * 192 / 4;      // 9216 float4 per channel slice
constexpr int NCH      = 18;
constexpr int PRED_CH  = 54;
constexpr int TGT_CH   = 6;

constexpr int TPB      = 256;
constexpr int SPLIT    = 4;                  // hw chunks per slice
constexpr int CHUNK4   = HW4 / SPLIT;        // 2304 float4 per block
constexpr int ITERS    = CHUNK4 / TPB;       // 9 stages
constexpr int NSLICES  = B * NCH;            // 288
constexpr int NBLOCKS  = NSLICES * SPLIT;    // 1152 (one wave @ 8 blk/SM)

constexpr int STAGES     = 3;                // TMA ring depth
constexpr int STAGE_B    = TPB * 16;         // 4096 bytes per tensor per stage
constexpr int STAGE_TX   = 2 * STAGE_B;      // 8192 bytes per stage
}

__device__ float        g_partials[NBLOCKS];
__device__ unsigned int g_count = 0;

__device__ __forceinline__ uint32_t smem_u32(const void* p) {
    return (uint32_t)__cvta_generic_to_shared(p);
}

__device__ __forceinline__ void bulk_g2s(void* smem_dst, const void* gmem_src,
                                         int bytes, uint32_t mbar) {
    asm volatile(
        "cp.async.bulk.shared::cluster.global.mbarrier::complete_tx::bytes "
        "[%0], [%1], %2, [%3];"
        :: "r"(smem_u32(smem_dst)), "l"(gmem_src), "r"(bytes), "r"(mbar)
        : "memory");
}

__device__ __forceinline__ void mbar_init(uint32_t mbar, uint32_t cnt) {
    asm volatile("mbarrier.init.shared.b64 [%0], %1;" :: "r"(mbar), "r"(cnt)
                 : "memory");
}
__device__ __forceinline__ void mbar_expect_tx(uint32_t mbar, uint32_t bytes) {
    asm volatile("mbarrier.arrive.expect_tx.shared.b64 _, [%0], %1;"
                 :: "r"(mbar), "r"(bytes) : "memory");
}
__device__ __forceinline__ void mbar_wait(uint32_t mbar, uint32_t parity) {
    asm volatile(
        "{\n\t"
        ".reg .pred P;\n\t"
        "WL_%=:\n\t"
        "mbarrier.try_wait.parity.acquire.cta.shared::cta.b64 P, [%0], %1;\n\t"
        "@P bra.uni WD_%=;\n\t"
        "bra.uni WL_%=;\n\t"
        "WD_%=:\n\t"
        "}"
        :: "r"(mbar), "r"(parity) : "memory");
}

__device__ __forceinline__ float block_reduce(float acc) {
    #pragma unroll
    for (int o = 16; o > 0; o >>= 1)
        acc += __shfl_xor_sync(0xffffffffu, acc, o);
    __shared__ float s[TPB / 32];
    if ((threadIdx.x & 31) == 0) s[threadIdx.x >> 5] = acc;
    __syncthreads();
    float v = 0.0f;
    if (threadIdx.x < 32) {
        v = (threadIdx.x < TPB / 32) ? s[threadIdx.x] : 0.0f;
        #pragma unroll
        for (int o = 4; o > 0; o >>= 1)
            v += __shfl_xor_sync(0xffffffffu, v, o);
    }
    return v;  // valid in thread 0
}

__global__ __launch_bounds__(TPB, 8)
void rpn_bce_fused(const float4* __restrict__ pred,
                   const float4* __restrict__ target,
                   float* __restrict__ out) {
    __shared__ float4 s_p[STAGES][TPB];                // 12 KB
    __shared__ float4 s_t[STAGES][TPB];                // 12 KB
    __shared__ __align__(8) unsigned long long mbar[STAGES];

    const int tid   = threadIdx.x;
    const int bid   = blockIdx.x;
    const int chunk = bid % SPLIT;
    const int slice = bid / SPLIT;           // 0..287
    const int ch    = slice % NCH;           // pred channel 0..17
    const int b     = slice / NCH;

    const float4* __restrict__ p =
        pred + ((size_t)b * PRED_CH + ch) * HW4 + (size_t)chunk * CHUNK4;
    const float4* __restrict__ t =
        target + ((size_t)b * TGT_CH + (ch & 1)) * HW4 + (size_t)chunk * CHUNK4;

    if (tid == 0) {
        #pragma unroll
        for (int s = 0; s < STAGES; ++s)
            mbar_init(smem_u32(&mbar[s]), 1);
    }
    __syncthreads();   // mbarriers visible before any TMA targets them

    // Prologue: fill all STAGES buffers.
    if (tid == 0) {
        #pragma unroll
        for (int s = 0; s < STAGES; ++s) {
            mbar_expect_tx(smem_u32(&mbar[s]), STAGE_TX);
            bulk_g2s(&s_p[s][0], p + s * TPB, STAGE_B, smem_u32(&mbar[s]));
            bulk_g2s(&s_t[s][0], t + s * TPB, STAGE_B, smem_u32(&mbar[s]));
        }
    }

    constexpr float NL2E = -1.44269504088896341f;  // -log2(e)
    float acc  = 0.0f;   // sum of max(x,0) - x*t
    float lacc = 0.0f;   // sum of log2( prod4 (1+e) )

    #pragma unroll
    for (int i = 0; i < ITERS; ++i) {
        const int s      = i % STAGES;
        const uint32_t parity = (uint32_t)((i / STAGES) & 1);

        mbar_wait(smem_u32(&mbar[s]), parity);

        const float4 x = s_p[s][tid];
        const float4 y = s_t[s][tid];

        const float e0 = exp2f(fabsf(x.x) * NL2E);
        const float e1 = exp2f(fabsf(x.y) * NL2E);
        const float e2 = exp2f(fabsf(x.z) * NL2E);
        const float e3 = exp2f(fabsf(x.w) * NL2E);

        float pr = 1.0f + e0;
        pr = fmaf(pr, e1, pr);
        pr = fmaf(pr, e2, pr);
        pr = fmaf(pr, e3, pr);
        lacc += __log2f(pr);                 // one LG2 per 4 elements

        acc += fmaxf(x.x, 0.0f); acc = fmaf(-x.x, y.x, acc);
        acc += fmaxf(x.y, 0.0f); acc = fmaf(-x.y, y.y, acc);
        acc += fmaxf(x.z, 0.0f); acc = fmaf(-x.z, y.z, acc);
        acc += fmaxf(x.w, 0.0f); acc = fmaf(-x.w, y.w, acc);

        // All threads finished reading buffer s -> safe to refill for i+STAGES.
        __syncthreads();
        if (tid == 0 && (i + STAGES) < ITERS) {
            mbar_expect_tx(smem_u32(&mbar[s]), STAGE_TX);
            bulk_g2s(&s_p[s][0], p + (i + STAGES) * TPB, STAGE_B,
                     smem_u32(&mbar[s]));
            bulk_g2s(&s_t[s][0], t + (i + STAGES) * TPB, STAGE_B,
                     smem_u32(&mbar[s]));
        }
    }

    const float v = block_reduce(fmaf(0.693147180559945f, lacc, acc));

    // Last-block-done deterministic finalize.
    __shared__ bool s_last;
    if (tid == 0) {
        g_partials[bid] = v;
        __threadfence();
        unsigned int n = atomicAdd(&g_count, 1u);
        s_last = (n == (unsigned int)(NBLOCKS - 1));
    }
    __syncthreads();

    if (s_last) {
        __threadfence();
        float a = 0.0f;
        #pragma unroll
        for (int i = tid; i < NBLOCKS; i += TPB)
            a += g_partials[i];
        const float total = block_reduce(a);
        if (tid == 0) {
            out[0] = total * (1.0f / 9.0f);  // / NUM_OBJ_CLS
            g_count = 0;                     // reset for graph replays
        }
    }
}

extern "C" void kernel_launch(void* const* d_in, const int* in_sizes, int n_in,
                              void* d_out, int out_size) {
    (void)in_sizes; (void)n_in; (void)out_size;
    const float4* pred   = (const float4*)d_in[0];
    const float4* target = (const float4*)d_in[1];
    float* out = (float*)d_out;

    rpn_bce_fused<<<NBLOCKS, TPB>>>(pred, target, out);
}

// round 11
// speedup vs baseline: 1.4742x; 1.3514x over previous
#include <cuda_runtime.h>
#include <cuda_bf16.h>

// pred (16,54,192,192) f32, target (16,6,192,192) f32, loc unused.
// loss = [ bce_sum(pred[:,0:18:2], target[:,0:1]) +
//          bce_sum(pred[:,1:18:2], target[:,1:2]) ] / 9
// Pred channel ch (0..17) pairs with target channel (ch & 1).
// Per element: max(x,0) - x*t + log1p(exp(-|x|)).
// Factored per pixel & parity: sum_c softplus(x_c)  -  t * sum_c x_c,
// and sum_i log1p(e_i) = ln( prod4 (1+e_i) ) -> one LG2 per float4.

namespace {
constexpr int B        = 16;
constexpr int HW4      = 192 * 192 / 4;      // 9216 float4 per channel slice
constexpr int NPAIR    = 9;                  // channels per parity
constexpr int PRED_CH  = 54;
constexpr int TGT_CH   = 6;

constexpr int TPB      = 256;
constexpr int CHUNKS   = HW4 / TPB;          // 36 pixel chunks per (b,parity)
constexpr int NBLOCKS  = B * 2 * CHUNKS;     // 1152 (one wave @ 8 blk/SM)
}

__device__ float        g_partials[NBLOCKS];
__device__ unsigned int g_count = 0;

__device__ __forceinline__ float block_reduce(float acc) {
    #pragma unroll
    for (int o = 16; o > 0; o >>= 1)
        acc += __shfl_xor_sync(0xffffffffu, acc, o);
    __shared__ float s[TPB / 32];
    if ((threadIdx.x & 31) == 0) s[threadIdx.x >> 5] = acc;
    __syncthreads();
    float v = 0.0f;
    if (threadIdx.x < 32) {
        v = (threadIdx.x < TPB / 32) ? s[threadIdx.x] : 0.0f;
        #pragma unroll
        for (int o = 4; o > 0; o >>= 1)
            v += __shfl_xor_sync(0xffffffffu, v, o);
    }
    return v;  // valid in thread 0
}

__global__ __launch_bounds__(TPB, 6)   // allow up to ~42 regs
void rpn_bce_fused(const float4* __restrict__ pred,
                   const float4* __restrict__ target,
                   float* __restrict__ out) {
    const int tid    = threadIdx.x;
    const int bid    = blockIdx.x;               // 0..1151
    const int chunk  = bid % CHUNKS;             // 0..35
    const int bp     = bid / CHUNKS;             // 0..31
    const int parity = bp & 1;
    const int b      = bp >> 1;

    const int pix = chunk * TPB + tid;           // float4 pixel index

    const float4* __restrict__ p =
        pred + ((size_t)b * PRED_CH + parity) * HW4 + pix;   // + c*2*HW4
    const float4 t =
        __ldg(target + ((size_t)b * TGT_CH + parity) * HW4 + pix);

    constexpr float NL2E = -1.44269504088896341f;  // -log2(e)

    float4 sp = make_float4(0.f, 0.f, 0.f, 0.f);   // sum max(x,0)
    float4 xs = make_float4(0.f, 0.f, 0.f, 0.f);   // sum x
    float  lacc = 0.0f;                             // sum log2(prod4(1+e))

    // 9 sequential, independent, fully-coalesced channel loads.
    #pragma unroll
    for (int c = 0; c < NPAIR; ++c) {
        const float4 x = __ldg(p + (size_t)c * (2 * HW4));

        const float e0 = exp2f(fabsf(x.x) * NL2E);
        const float e1 = exp2f(fabsf(x.y) * NL2E);
        const float e2 = exp2f(fabsf(x.z) * NL2E);
        const float e3 = exp2f(fabsf(x.w) * NL2E);

        float pr = 1.0f + e0;
        pr = fmaf(pr, e1, pr);
        pr = fmaf(pr, e2, pr);
        pr = fmaf(pr, e3, pr);
        lacc += __log2f(pr);               // one LG2 per 4 elements

        sp.x += fmaxf(x.x, 0.0f);  xs.x += x.x;
        sp.y += fmaxf(x.y, 0.0f);  xs.y += x.y;
        sp.z += fmaxf(x.z, 0.0f);  xs.z += x.z;
        sp.w += fmaxf(x.w, 0.0f);  xs.w += x.w;
    }

    // total = sum sp - t . xs + ln2 * lacc   (target multiplied once per 9 ch)
    float acc = sp.x + sp.y + sp.z + sp.w;
    acc = fmaf(-t.x, xs.x, acc);
    acc = fmaf(-t.y, xs.y, acc);
    acc = fmaf(-t.z, xs.z, acc);
    acc = fmaf(-t.w, xs.w, acc);
    acc = fmaf(0.693147180559945f, lacc, acc);

    const float v = block_reduce(acc);

    // Last-block-done deterministic finalize.
    __shared__ bool s_last;
    if (tid == 0) {
        g_partials[bid] = v;
        __threadfence();
        unsigned int n = atomicAdd(&g_count, 1u);
        s_last = (n == (unsigned int)(NBLOCKS - 1));
    }
    __syncthreads();

    if (s_last) {
        __threadfence();
        float a = 0.0f;
        #pragma unroll
        for (int i = tid; i < NBLOCKS; i += TPB)
            a += g_partials[i];
        const float total = block_reduce(a);
        if (tid == 0) {
            out[0] = total * (1.0f / 9.0f);   // / NUM_OBJ_CLS
            g_count = 0;                      // reset for graph replays
        }
    }
}

extern "C" void kernel_launch(void* const* d_in, const int* in_sizes, int n_in,
                              void* d_out, int out_size) {
    (void)in_sizes; (void)n_in; (void)out_size;
    const float4* pred   = (const float4*)d_in[0];
    const float4* target = (const float4*)d_in[1];
    float* out = (float*)d_out;

    rpn_bce_fused<<<NBLOCKS, TPB>>>(pred, target, out);
}

// round 12
// speedup vs baseline: 1.5000x; 1.0175x over previous
#include <cuda_runtime.h>
#include <cuda_bf16.h>

// pred (16,54,192,192) f32, target (16,6,192,192) f32, loc unused.
// loss = [ bce_sum(pred[:,0:18:2], target[:,0:1]) +
//          bce_sum(pred[:,1:18:2], target[:,1:2]) ] / 9
// Pred channel ch (0..17) pairs with target channel (ch & 1).
// Per element: max(x,0) - x*t + log1p(exp(-|x|)).
// log trick: sum_i log1p(e_i) = ln( prod4 (1+e_i) ) -> one LG2 per float4.
//
// Schedule: flat grid-stride over the compacted (16 x 18 x 9216) float4 view
// with exactly 148*8 blocks -> every SM gets 8 CTAs (no 7-vs-8 CTA tail).

namespace {
constexpr int B        = 16;
constexpr int HW4      = 192 * 192 / 4;      // 9216 float4 per channel slice
constexpr int NCH      = 18;
constexpr int PRED_CH  = 54;
constexpr int TGT_CH   = 6;

constexpr int TPB      = 256;
constexpr int NBLOCKS  = 148 * 8;            // 1184: exactly 8 CTAs per SM
constexpr int TOTAL4   = B * NCH * HW4;      // 2,654,208 float4 elements
constexpr int STRIDE   = NBLOCKS * TPB;      // 303,104
constexpr int FULL_IT  = TOTAL4 / STRIDE;    // 8 full sweeps
constexpr int REM      = TOTAL4 - FULL_IT * STRIDE;  // 229,376 tail threads
}

__device__ float        g_partials[NBLOCKS];
__device__ unsigned int g_count = 0;

__device__ __forceinline__ float block_reduce(float acc) {
    #pragma unroll
    for (int o = 16; o > 0; o >>= 1)
        acc += __shfl_xor_sync(0xffffffffu, acc, o);
    __shared__ float s[TPB / 32];
    if ((threadIdx.x & 31) == 0) s[threadIdx.x >> 5] = acc;
    __syncthreads();
    float v = 0.0f;
    if (threadIdx.x < 32) {
        v = (threadIdx.x < TPB / 32) ? s[threadIdx.x] : 0.0f;
        #pragma unroll
        for (int o = 4; o > 0; o >>= 1)
            v += __shfl_xor_sync(0xffffffffu, v, o);
    }
    return v;  // valid in thread 0
}

__device__ __forceinline__ void bce4(const float4 x, const float4 y,
                                     float& acc, float& lacc) {
    constexpr float NL2E = -1.44269504088896341f;  // -log2(e)
    const float e0 = exp2f(fabsf(x.x) * NL2E);
    const float e1 = exp2f(fabsf(x.y) * NL2E);
    const float e2 = exp2f(fabsf(x.z) * NL2E);
    const float e3 = exp2f(fabsf(x.w) * NL2E);

    float pr = 1.0f + e0;                 // prod4 (1+e_i) in (1,16]
    pr = fmaf(pr, e1, pr);
    pr = fmaf(pr, e2, pr);
    pr = fmaf(pr, e3, pr);
    lacc += __log2f(pr);                  // one LG2 per 4 elements

    acc += fmaxf(x.x, 0.0f); acc = fmaf(-x.x, y.x, acc);
    acc += fmaxf(x.y, 0.0f); acc = fmaf(-x.y, y.y, acc);
    acc += fmaxf(x.z, 0.0f); acc = fmaf(-x.z, y.z, acc);
    acc += fmaxf(x.w, 0.0f); acc = fmaf(-x.w, y.w, acc);
}

// Decode flat compacted index f (0..TOTAL4) into pred/target float4 offsets.
__device__ __forceinline__ void decode(int f, int& poff, int& toff) {
    const int b   = f / (NCH * HW4);            // const-div -> umulhi
    const int r   = f - b * (NCH * HW4);
    const int ch  = r / HW4;
    const int pix = r - ch * HW4;
    poff = (b * PRED_CH + ch) * HW4 + pix;
    toff = (b * TGT_CH + (ch & 1)) * HW4 + pix;
}

__global__ __launch_bounds__(TPB, 8)   // keep regs <= 32, 8 CTAs/SM
void rpn_bce_fused(const float4* __restrict__ pred,
                   const float4* __restrict__ target,
                   float* __restrict__ out) {
    const int tid  = threadIdx.x;
    const int bid  = blockIdx.x;
    const int base = bid * TPB + tid;

    float acc  = 0.0f;
    float lacc = 0.0f;

    #pragma unroll
    for (int i = 0; i < FULL_IT; ++i) {
        const int f = base + i * STRIDE;
        int poff, toff;
        decode(f, poff, toff);
        const float4 x = __ldg(pred + poff);
        const float4 y = __ldg(target + toff);
        bce4(x, y, acc, lacc);
    }
    // tail sweep (first REM threads)
    if (base < REM) {
        const int f = base + FULL_IT * STRIDE;
        int poff, toff;
        decode(f, poff, toff);
        const float4 x = __ldg(pred + poff);
        const float4 y = __ldg(target + toff);
        bce4(x, y, acc, lacc);
    }

    const float v = block_reduce(fmaf(0.693147180559945f, lacc, acc));

    // Last-block-done deterministic finalize.
    __shared__ bool s_last;
    if (tid == 0) {
        g_partials[bid] = v;
        __threadfence();
        unsigned int n = atomicAdd(&g_count, 1u);
        s_last = (n == (unsigned int)(NBLOCKS - 1));
    }
    __syncthreads();

    if (s_last) {
        __threadfence();
        float a = 0.0f;
        #pragma unroll
        for (int i = tid; i < NBLOCKS; i += TPB)
            a += g_partials[i];
        const float total = block_reduce(a);
        if (tid == 0) {
            out[0] = total * (1.0f / 9.0f);   // / NUM_OBJ_CLS
            g_count = 0;                      // reset for graph replays
        }
    }
}

extern "C" void kernel_launch(void* const* d_in, const int* in_sizes, int n_in,
                              void* d_out, int out_size) {
    (void)in_sizes; (void)n_in; (void)out_size;
    const float4* pred   = (const float4*)d_in[0];
    const float4* target = (const float4*)d_in[1];
    float* out = (float*)d_out;

    rpn_bce_fused<<<NBLOCKS, TPB>>>(pred, target, out);
}

// round 14
// speedup vs baseline: 1.5345x; 1.0230x over previous
#include <cuda_runtime.h>
#include <cuda_bf16.h>

// pred (16,54,192,192) f32, target (16,6,192,192) f32, loc unused.
// loss = [ bce_sum(pred[:,0:18:2], target[:,0:1]) +
//          bce_sum(pred[:,1:18:2], target[:,1:2]) ] / 9
// Per element: max(x,0) - x*t + log1p(exp(-|x|)).
// Factoring: per pixel, sum_c [max-term + log-term] - t0*sum_c x_even
//                                                   - t1*sum_c x_odd,
// so target is loaded ONCE per pixel (L2 traffic 85 MB -> 47 MB).
// log trick: sum_i log1p(e_i) = ln( prod8 (1+e_i) ), e in (0,1] ->
// prod8 in (1,256] (exact in f32) -> one LG2 per 8 elements.

namespace {
constexpr int B        = 16;
constexpr int HW4      = 192 * 192 / 4;      // 9216 float4 per channel slice
constexpr int NPAIR    = 9;
constexpr int PRED_CH  = 54;
constexpr int TGT_CH   = 6;

constexpr int TPB      = 128;
constexpr int CHUNKS   = HW4 / TPB;          // 72 pixel chunks per batch
constexpr int NBLOCKS  = B * CHUNKS;         // 1152 blocks, 16 CTA/SM -> all resident
}

__device__ float        g_partials[NBLOCKS];
__device__ unsigned int g_count = 0;

__device__ __forceinline__ float block_reduce(float acc) {
    #pragma unroll
    for (int o = 16; o > 0; o >>= 1)
        acc += __shfl_xor_sync(0xffffffffu, acc, o);
    __shared__ float s[TPB / 32];
    if ((threadIdx.x & 31) == 0) s[threadIdx.x >> 5] = acc;
    __syncthreads();
    float v = 0.0f;
    if (threadIdx.x < 32) {
        v = (threadIdx.x < TPB / 32) ? s[threadIdx.x] : 0.0f;
        #pragma unroll
        for (int o = 2; o > 0; o >>= 1)
            v += __shfl_xor_sync(0xffffffffu, v, o);
    }
    return v;  // valid in thread 0
}

__global__ __launch_bounds__(TPB, 16)   // cap regs at 32 -> 64 warps/SM
void rpn_bce_fused(const float4* __restrict__ pred,
                   const float4* __restrict__ target,
                   float* __restrict__ out) {
    const int tid   = threadIdx.x;
    const int bid   = blockIdx.x;                // 0..1151
    const int chunk = bid % CHUNKS;              // 0..71
    const int b     = bid / CHUNKS;              // 0..15

    const int pix = chunk * TPB + tid;           // float4 pixel index

    const float4* __restrict__ p =
        pred + (size_t)b * PRED_CH * HW4 + pix;  // channel c at + c*HW4

    constexpr float NL2E = -1.44269504088896341f;  // -log2(e)

    float acc  = 0.0f;                 // sum of max(x,0)
    float lacc = 0.0f;                 // sum of log2(prod8(1+e))
    float4 xs0 = make_float4(0.f, 0.f, 0.f, 0.f);   // sum x, even channels
    float4 xs1 = make_float4(0.f, 0.f, 0.f, 0.f);   // sum x, odd channels

    #pragma unroll
    for (int c = 0; c < NPAIR; ++c) {
        const float4 x0 = __ldg(p + (size_t)(2 * c)     * HW4);
        const float4 x1 = __ldg(p + (size_t)(2 * c + 1) * HW4);

        const float ea = exp2f(fabsf(x0.x) * NL2E);
        const float eb = exp2f(fabsf(x0.y) * NL2E);
        const float ec = exp2f(fabsf(x0.z) * NL2E);
        const float ed = exp2f(fabsf(x0.w) * NL2E);
        const float ee = exp2f(fabsf(x1.x) * NL2E);
        const float ef = exp2f(fabsf(x1.y) * NL2E);
        const float eg = exp2f(fabsf(x1.z) * NL2E);
        const float eh = exp2f(fabsf(x1.w) * NL2E);

        float pr = 1.0f + ea;          // prod8 (1+e_i) in (1,256]
        pr = fmaf(pr, eb, pr);
        pr = fmaf(pr, ec, pr);
        pr = fmaf(pr, ed, pr);
        pr = fmaf(pr, ee, pr);
        pr = fmaf(pr, ef, pr);
        pr = fmaf(pr, eg, pr);
        pr = fmaf(pr, eh, pr);
        lacc += __log2f(pr);           // one LG2 per 8 elements

        acc += fmaxf(x0.x, 0.0f) + fmaxf(x0.y, 0.0f)
             + fmaxf(x0.z, 0.0f) + fmaxf(x0.w, 0.0f)
             + fmaxf(x1.x, 0.0f) + fmaxf(x1.y, 0.0f)
             + fmaxf(x1.z, 0.0f) + fmaxf(x1.w, 0.0f);

        xs0.x += x0.x; xs0.y += x0.y; xs0.z += x0.z; xs0.w += x0.w;
        xs1.x += x1.x; xs1.y += x1.y; xs1.z += x1.z; xs1.w += x1.w;
    }

    // Target loaded once per pixel, AFTER the loop (not live in mainloop).
    const float4 t0 = __ldg(target + ((size_t)b * TGT_CH + 0) * HW4 + pix);
    const float4 t1 = __ldg(target + ((size_t)b * TGT_CH + 1) * HW4 + pix);

    acc = fmaf(-t0.x, xs0.x, acc);
    acc = fmaf(-t0.y, xs0.y, acc);
    acc = fmaf(-t0.z, xs0.z, acc);
    acc = fmaf(-t0.w, xs0.w, acc);
    acc = fmaf(-t1.x, xs1.x, acc);
    acc = fmaf(-t1.y, xs1.y, acc);
    acc = fmaf(-t1.z, xs1.z, acc);
    acc = fmaf(-t1.w, xs1.w, acc);
    acc = fmaf(0.693147180559945f, lacc, acc);

    const float v = block_reduce(acc);

    // Last-block-done deterministic finalize.
    __shared__ bool s_last;
    if (tid == 0) {
        g_partials[bid] = v;
        __threadfence();
        unsigned int n = atomicAdd(&g_count, 1u);
        s_last = (n == (unsigned int)(NBLOCKS - 1));
    }
    __syncthreads();

    if (s_last) {
        __threadfence();
        float a = 0.0f;
        #pragma unroll
        for (int i = tid; i < NBLOCKS; i += TPB)
            a += g_partials[i];
        const float total = block_reduce(a);
        if (tid == 0) {
            out[0] = total * (1.0f / 9.0f);   // / NUM_OBJ_CLS
            g_count = 0;                      // reset for graph replays
        }
    }
}

extern "C" void kernel_launch(void* const* d_in, const int* in_sizes, int n_in,
                              void* d_out, int out_size) {
    (void)in_sizes; (void)n_in; (void)out_size;
    const float4* pred   = (const float4*)d_in[0];
    const float4* target = (const float4*)d_in[1];
    float* out = (float*)d_out;

    rpn_bce_fused<<<NBLOCKS, TPB>>>(pred, target, out);
}